// round 1
// baseline (speedup 1.0000x reference)
#include <cuda_runtime.h>
#include <math.h>

// Problem constants
#define SS 128          // msa rows
#define QQ 256          // residues
#define CC 256          // c_qkv
#define HH 8            // heads
#define CHD 32          // c_hidden per head
#define MROWS (SS*QQ)   // 32768

// Scratch (device globals: allocation-free rule)
__device__ float g_wpack[1024 * 256];            // stacked wq|wk|wv|wg, wq pre-scaled
__device__ float g_q[SS * HH * QQ * CHD];        // [s,h,q,d]
__device__ float g_k[SS * HH * QQ * CHD];
__device__ float g_v[SS * HH * QQ * CHD];
__device__ float g_gpre[MROWS * 256];            // gate pre-activation [s*Q+q, e]
__device__ float g_o[MROWS * 256];               // gated attention output [s*Q+q, e]

// ---------------------------------------------------------------------------
// Pack the four projection weights into one [1024, 256] matrix.
// wq rows are pre-scaled by 1/sqrt(CH) so attention logits come out scaled.
// ---------------------------------------------------------------------------
__global__ void pack_weights(const float* __restrict__ wq, const float* __restrict__ wk,
                             const float* __restrict__ wv, const float* __restrict__ wg) {
    int e = blockIdx.x;     // 0..1023
    int c = threadIdx.x;    // 0..255
    float val;
    if (e < 256)       val = wq[e * 256 + c] * 0.17677669529663687f; // 1/sqrt(32)
    else if (e < 512)  val = wk[(e - 256) * 256 + c];
    else if (e < 768)  val = wv[(e - 512) * 256 + c];
    else               val = wg[(e - 768) * 256 + c];
    g_wpack[e * 256 + c] = val;
}

// ---------------------------------------------------------------------------
// GEMM 1: Y[M=32768, N=1024] = X[M,256] * Wpack^T (both K-major, NT gemm).
// 64x64 tile, 256 threads, 4x4 micro-tile. Epilogue scatters into the
// per-head [s,h,q,d] layouts for q/k/v and [row,e] for the gate prelogits.
// ---------------------------------------------------------------------------
__global__ __launch_bounds__(256) void gemm_qkvg(const float* __restrict__ X,
                                                 const float* __restrict__ bg) {
    __shared__ float As[16][64];
    __shared__ float Bs[16][64];
    const int bm = blockIdx.y * 64;
    const int bn = blockIdx.x * 64;
    const int tid = threadIdx.x;
    const int tx = tid & 15, ty = tid >> 4;

    float acc[4][4] = {};
    for (int k0 = 0; k0 < 256; k0 += 16) {
        #pragma unroll
        for (int i = 0; i < 4; i++) {
            int idx = tid + i * 256;
            int r = idx >> 4, c = idx & 15;
            As[c][r] = X[(bm + r) * 256 + k0 + c];
            Bs[c][r] = g_wpack[(bn + r) * 256 + k0 + c];
        }
        __syncthreads();
        #pragma unroll
        for (int kk = 0; kk < 16; kk++) {
            float a[4], b[4];
            #pragma unroll
            for (int i = 0; i < 4; i++) a[i] = As[kk][ty * 4 + i];
            #pragma unroll
            for (int j = 0; j < 4; j++) b[j] = Bs[kk][tx * 4 + j];
            #pragma unroll
            for (int i = 0; i < 4; i++)
                #pragma unroll
                for (int j = 0; j < 4; j++) acc[i][j] = fmaf(a[i], b[j], acc[i][j]);
        }
        __syncthreads();
    }

    #pragma unroll
    for (int i = 0; i < 4; i++) {
        int r = bm + ty * 4 + i;
        int s = r >> 8, q = r & 255;
        #pragma unroll
        for (int j = 0; j < 4; j++) {
            int e = bn + tx * 4 + j;
            float val = acc[i][j];
            if (e < 768) {
                int which = e >> 8;
                int h = (e >> 5) & 7;
                int d = e & 31;
                float* dst = (which == 0) ? g_q : ((which == 1) ? g_k : g_v);
                dst[((s * HH + h) * QQ + q) * CHD + d] = val;
            } else {
                int eg = e - 768;
                g_gpre[r * 256 + eg] = val + bg[eg];
            }
        }
    }
}

// ---------------------------------------------------------------------------
// Attention: one block per (s,h). K/V tiles staged in 64KB dynamic smem.
// Thread t owns query q=t: pass 1 finds the row max, pass 2 accumulates
// exp-weighted V and the normalizer in one sweep. Gate fused in epilogue.
// ---------------------------------------------------------------------------
__global__ __launch_bounds__(256) void attn_kernel(const float* __restrict__ bias,
                                                   const float* __restrict__ mask) {
    extern __shared__ float sm[];
    float* ks = sm;            // [256][32]
    float* vs = sm + 8192;     // [256][32]

    const int s = blockIdx.x >> 3;
    const int h = blockIdx.x & 7;
    const int t = threadIdx.x;  // query index

    const float4* kb = (const float4*)(g_k + ((size_t)(s * HH + h) * QQ) * CHD);
    const float4* vb = (const float4*)(g_v + ((size_t)(s * HH + h) * QQ) * CHD);
    for (int i = t; i < 2048; i += 256) {
        ((float4*)ks)[i] = kb[i];
        ((float4*)vs)[i] = vb[i];
    }
    __syncthreads();

    float qv[32];
    const float4* qb = (const float4*)(g_q + ((size_t)((s * HH + h) * QQ) + t) * CHD);
    #pragma unroll
    for (int i = 0; i < 8; i++) ((float4*)qv)[i] = qb[i];

    const float* brow = bias + ((size_t)h * QQ + t) * QQ;
    const float* mrow = mask + (size_t)s * QQ;

    // pass 1: row max
    float m = -3.0e38f;
    for (int j = 0; j < 256; j++) {
        float dot = 0.f;
        #pragma unroll
        for (int d = 0; d < 32; d++) dot = fmaf(qv[d], ks[j * 32 + d], dot);
        float logit = dot + brow[j] + (mrow[j] - 1.0f) * 1e9f;
        m = fmaxf(m, logit);
    }

    // pass 2: exp-weighted accumulate
    float o[32];
    #pragma unroll
    for (int d = 0; d < 32; d++) o[d] = 0.f;
    float l = 0.f;
    for (int j = 0; j < 256; j++) {
        float dot = 0.f;
        #pragma unroll
        for (int d = 0; d < 32; d++) dot = fmaf(qv[d], ks[j * 32 + d], dot);
        float logit = dot + brow[j] + (mrow[j] - 1.0f) * 1e9f;
        float w = __expf(logit - m);
        l += w;
        #pragma unroll
        for (int d = 0; d < 32; d++) o[d] = fmaf(w, vs[j * 32 + d], o[d]);
    }

    // epilogue: normalize, sigmoid gate, store to [s*Q+q, h*CH+d]
    float inv_l = 1.0f / l;
    const int row = (s << 8) + t;
    const float* gp = g_gpre + (size_t)row * 256 + h * CHD;
    float*       op = g_o    + (size_t)row * 256 + h * CHD;
    #pragma unroll
    for (int d = 0; d < 32; d++) {
        float gate = 1.0f / (1.0f + __expf(-gp[d]));
        op[d] = o[d] * inv_l * gate;
    }
}

// ---------------------------------------------------------------------------
// GEMM 2: out[q,s,c] = add[q,s,c] + sum_e g_o[s*Q+q, e] * wo[c, e] + bo[c]
// Same NT tiling; epilogue does the (s,q) transpose + residual + bias.
// ---------------------------------------------------------------------------
__global__ __launch_bounds__(256) void gemm_out(const float* __restrict__ wo,
                                                const float* __restrict__ bo,
                                                const float* __restrict__ addt,
                                                float* __restrict__ out) {
    __shared__ float As[16][64];
    __shared__ float Bs[16][64];
    const int bm = blockIdx.y * 64;
    const int bn = blockIdx.x * 64;
    const int tid = threadIdx.x;
    const int tx = tid & 15, ty = tid >> 4;

    float acc[4][4] = {};
    for (int k0 = 0; k0 < 256; k0 += 16) {
        #pragma unroll
        for (int i = 0; i < 4; i++) {
            int idx = tid + i * 256;
            int r = idx >> 4, c = idx & 15;
            As[c][r] = g_o[(size_t)(bm + r) * 256 + k0 + c];
            Bs[c][r] = wo[(bn + r) * 256 + k0 + c];
        }
        __syncthreads();
        #pragma unroll
        for (int kk = 0; kk < 16; kk++) {
            float a[4], b[4];
            #pragma unroll
            for (int i = 0; i < 4; i++) a[i] = As[kk][ty * 4 + i];
            #pragma unroll
            for (int j = 0; j < 4; j++) b[j] = Bs[kk][tx * 4 + j];
            #pragma unroll
            for (int i = 0; i < 4; i++)
                #pragma unroll
                for (int j = 0; j < 4; j++) acc[i][j] = fmaf(a[i], b[j], acc[i][j]);
        }
        __syncthreads();
    }

    #pragma unroll
    for (int i = 0; i < 4; i++) {
        int r = bm + ty * 4 + i;
        int s = r >> 8, q = r & 255;
        #pragma unroll
        for (int j = 0; j < 4; j++) {
            int c = bn + tx * 4 + j;
            size_t oidx = ((size_t)q * SS + s) * CC + c;
            out[oidx] = addt[oidx] + acc[i][j] + bo[c];
        }
    }
}

// ---------------------------------------------------------------------------
extern "C" void kernel_launch(void* const* d_in, const int* in_sizes, int n_in,
                              void* d_out, int out_size) {
    const float* x    = (const float*)d_in[0];   // input_qkv [1,128,256,256]
    const float* mask = (const float*)d_in[1];   // [1,128,1,1,256]
    const float* bias = (const float*)d_in[2];   // [1,1,8,256,256]
    const float* addt = (const float*)d_in[3];   // [1,256,128,256]
    const float* wq   = (const float*)d_in[4];
    const float* wk   = (const float*)d_in[5];
    const float* wv   = (const float*)d_in[6];
    const float* wg   = (const float*)d_in[7];
    const float* bg   = (const float*)d_in[8];
    const float* wo   = (const float*)d_in[9];
    const float* bo   = (const float*)d_in[10];
    float* out = (float*)d_out;

    pack_weights<<<1024, 256>>>(wq, wk, wv, wg);
    gemm_qkvg<<<dim3(16, 512), 256>>>(x, bg);

    cudaFuncSetAttribute(attn_kernel, cudaFuncAttributeMaxDynamicSharedMemorySize, 65536);
    attn_kernel<<<1024, 256, 65536>>>(bias, mask);

    gemm_out<<<dim3(4, 512), 256>>>(wo, bo, addt, out);
}

// round 6
// speedup vs baseline: 4.9549x; 4.9549x over previous
#include <cuda_runtime.h>
#include <cuda_bf16.h>
#include <cstdint>
#include <math.h>

#define SS 128
#define QQ 256
#define CC 256
#define HH 8
#define CHD 32
#define MROWS (SS*QQ)

// ---------------------------------------------------------------------------
// Helpers
// ---------------------------------------------------------------------------
__device__ __forceinline__ uint32_t smem_u32(const void* p) {
    uint32_t a;
    asm("{ .reg .u64 t; cvta.to.shared.u64 t, %1; cvt.u32.u64 %0, t; }" : "=r"(a) : "l"(p));
    return a;
}
__device__ __forceinline__ void cp16(uint32_t dst, const void* src) {
    asm volatile("cp.async.cg.shared.global [%0], [%1], 16;" :: "r"(dst), "l"(src));
}
__device__ __forceinline__ void ldmx4(uint32_t* f, uint32_t addr) {
    asm volatile("ldmatrix.sync.aligned.m8n8.x4.shared.b16 {%0,%1,%2,%3}, [%4];"
                 : "=r"(f[0]), "=r"(f[1]), "=r"(f[2]), "=r"(f[3]) : "r"(addr));
}
__device__ __forceinline__ void mma16816(float* c, const uint32_t* a, uint32_t b0, uint32_t b1) {
    asm volatile("mma.sync.aligned.m16n8k16.row.col.f32.bf16.bf16.f32 "
                 "{%0,%1,%2,%3}, {%4,%5,%6,%7}, {%8,%9}, {%0,%1,%2,%3};"
                 : "+f"(c[0]), "+f"(c[1]), "+f"(c[2]), "+f"(c[3])
                 : "r"(a[0]), "r"(a[1]), "r"(a[2]), "r"(a[3]), "r"(b0), "r"(b1));
}
__device__ __forceinline__ void fma2(uint64_t& acc, uint64_t a, uint64_t b) {
    asm("fma.rn.f32x2 %0, %1, %2, %0;" : "+l"(acc) : "l"(a), "l"(b));
}

// ---------------------------------------------------------------------------
// Scratch (device globals: allocation-free rule)
// ---------------------------------------------------------------------------
__device__ __nv_bfloat16 g_xb[MROWS * 256];       // input in bf16
__device__ __nv_bfloat16 g_wb[1024 * 256];        // packed wq|wk|wv|wg (wq pre-scaled)
__device__ __nv_bfloat16 g_wob[256 * 256];        // wo in bf16
__device__ float g_q[SS * HH * QQ * CHD];         // [s,h,q,d]
__device__ float g_k[SS * HH * QQ * CHD];
__device__ float g_v[SS * HH * QQ * CHD];
__device__ float g_gate[MROWS * 256];             // sigmoid gate, [row, e]
__device__ __nv_bfloat16 g_ob[MROWS * 256];       // gated attention output (bf16)
__device__ float g_biast[HH * QQ * QQ];           // bias transposed: [h][j][q]

// ---------------------------------------------------------------------------
// Prologue conversions
// ---------------------------------------------------------------------------
__global__ void conv_x(const float* __restrict__ x) {
    int i = blockIdx.x * blockDim.x + threadIdx.x;  // per 4 elements
    float4 v = ((const float4*)x)[i];
    __nv_bfloat162* dst = (__nv_bfloat162*)g_xb;
    dst[2 * i]     = __floats2bfloat162_rn(v.x, v.y);
    dst[2 * i + 1] = __floats2bfloat162_rn(v.z, v.w);
}

__global__ void pack_w(const float* __restrict__ wq, const float* __restrict__ wk,
                       const float* __restrict__ wv, const float* __restrict__ wg,
                       const float* __restrict__ wo) {
    int e = blockIdx.x;
    int c = threadIdx.x;
    if (e < 1024) {
        float val;
        if (e < 256)      val = wq[e * 256 + c] * 0.17677669529663687f;
        else if (e < 512) val = wk[(e - 256) * 256 + c];
        else if (e < 768) val = wv[(e - 512) * 256 + c];
        else              val = wg[(e - 768) * 256 + c];
        g_wb[e * 256 + c] = __float2bfloat16(val);
    } else {
        int r = e - 1024;
        g_wob[r * 256 + c] = __float2bfloat16(wo[r * 256 + c]);
    }
}

__global__ void bias_tr(const float* __restrict__ bias) {
    __shared__ float t[32][33];
    int h = blockIdx.z;
    int q0 = blockIdx.y * 32, j0 = blockIdx.x * 32;
    t[threadIdx.y][threadIdx.x] =
        bias[((size_t)h * 256 + q0 + threadIdx.y) * 256 + j0 + threadIdx.x];
    __syncthreads();
    g_biast[((size_t)h * 256 + j0 + threadIdx.y) * 256 + q0 + threadIdx.x] =
        t[threadIdx.x][threadIdx.y];
}

// ---------------------------------------------------------------------------
// Shared GEMM core: C[128,128] = A[128,256] x B[128,256]^T (NT, bf16, f32 acc)
// 8 warps as 4(M) x 2(N); per warp 32x64 via 2 x 8 m16n8k16 tiles.
// Smem rows padded to 80B (40 bf16) -> ldmatrix conflict-free.
// Double-buffered cp.async over 8 K-iterations of BK=32.
// ---------------------------------------------------------------------------
#define TILE_B 10240   // 128 rows * 80 bytes

__device__ __forceinline__ void gemm_core(const __nv_bfloat16* __restrict__ gA,
                                          const __nv_bfloat16* __restrict__ gB,
                                          char* sA, char* sB,
                                          float acc[2][8][4]) {
    const int tid = threadIdx.x, lane = tid & 31, wid = tid >> 5;
    const int wm0 = (wid >> 1) * 32, wn0 = (wid & 1) * 64;
    const uint32_t aB = smem_u32(sA), bB = smem_u32(sB);

    #pragma unroll
    for (int mt = 0; mt < 2; mt++)
        #pragma unroll
        for (int nt = 0; nt < 8; nt++)
            #pragma unroll
            for (int i = 0; i < 4; i++) acc[mt][nt][i] = 0.f;

    // tile loader: 512 16B chunks per operand, 2 per thread
    auto load_tile = [&](int buf, int k0) {
        #pragma unroll
        for (int j = 0; j < 2; j++) {
            int idx = tid + j * 256;
            int r = idx >> 2, ch = idx & 3;
            uint32_t so = (uint32_t)(buf * TILE_B + r * 80 + ch * 16);
            const __nv_bfloat16* sa = gA + r * 256 + k0 + ch * 8;
            const __nv_bfloat16* sb = gB + r * 256 + k0 + ch * 8;
            cp16(aB + so, sa);
            cp16(bB + so, sb);
        }
        asm volatile("cp.async.commit_group;" ::: "memory");
    };

    load_tile(0, 0);
    for (int kit = 0; kit < 8; kit++) {
        if (kit < 7) {
            load_tile((kit + 1) & 1, (kit + 1) * 32);
            asm volatile("cp.async.wait_group 1;" ::: "memory");
        } else {
            asm volatile("cp.async.wait_group 0;" ::: "memory");
        }
        __syncthreads();
        const uint32_t ab = aB + (kit & 1) * TILE_B;
        const uint32_t bb = bB + (kit & 1) * TILE_B;
        #pragma unroll
        for (int kk = 0; kk < 2; kk++) {
            uint32_t af[2][4];
            #pragma unroll
            for (int mt = 0; mt < 2; mt++) {
                int row = wm0 + mt * 16 + (lane & 15);
                int col = kk * 16 + ((lane >> 4) << 3);
                ldmx4(af[mt], ab + row * 80 + col * 2);
            }
            #pragma unroll
            for (int nt2 = 0; nt2 < 4; nt2++) {
                uint32_t bf[4];
                int nrow = wn0 + nt2 * 16 + (lane & 7) + ((lane >> 4) << 3);
                int ncol = kk * 16 + (((lane >> 3) & 1) << 3);
                ldmx4(bf, bb + nrow * 80 + ncol * 2);
                #pragma unroll
                for (int mt = 0; mt < 2; mt++) {
                    mma16816(acc[mt][2 * nt2],     af[mt], bf[0], bf[1]);
                    mma16816(acc[mt][2 * nt2 + 1], af[mt], bf[2], bf[3]);
                }
            }
        }
        __syncthreads();
    }
}

// ---------------------------------------------------------------------------
// GEMM1: Y[32768,1024] = Xb @ Wb^T. Epilogue scatters q/k/v + sigmoid gate.
// grid (8, 256)
// ---------------------------------------------------------------------------
__global__ __launch_bounds__(256) void gemm1_mma(const float* __restrict__ bg) {
    __shared__ char sA[2 * TILE_B];
    __shared__ char sB[2 * TILE_B];
    const int bn = blockIdx.x, bm = blockIdx.y;
    const int lane = threadIdx.x & 31, wid = threadIdx.x >> 5;
    const int wm0 = (wid >> 1) * 32, wn0 = (wid & 1) * 64;

    float acc[2][8][4];
    gemm_core(g_xb + (size_t)bm * 128 * 256, g_wb + (size_t)bn * 128 * 256, sA, sB, acc);

    #pragma unroll
    for (int mt = 0; mt < 2; mt++) {
        #pragma unroll
        for (int nt = 0; nt < 8; nt++) {
            #pragma unroll
            for (int half = 0; half < 2; half++) {   // c0c1 (row+0) / c2c3 (row+8)
                int m = bm * 128 + wm0 + mt * 16 + (lane >> 2) + half * 8;
                int e = bn * 128 + wn0 + nt * 8 + 2 * (lane & 3);
                float v0 = acc[mt][nt][2 * half];
                float v1 = acc[mt][nt][2 * half + 1];
                int s = m >> 8, q = m & 255;
                if (e < 768) {
                    int which = e >> 8;
                    int h = (e >> 5) & 7;
                    int d = e & 31;
                    float* dst = (which == 0 ? g_q : (which == 1 ? g_k : g_v)) +
                                 ((size_t)(s * 8 + h) * 256 + q) * 32 + d;
                    *(float2*)dst = make_float2(v0, v1);
                } else {
                    int eg = e - 768;
                    float g0 = 1.0f / (1.0f + __expf(-(v0 + bg[eg])));
                    float g1 = 1.0f / (1.0f + __expf(-(v1 + bg[eg + 1])));
                    *(float2*)(g_gate + (size_t)m * 256 + eg) = make_float2(g0, g1);
                }
            }
        }
    }
}

// ---------------------------------------------------------------------------
// GEMM2: out[q,s,c] = addt + g_ob @ wo^T + bo. grid (2, 256)
// ---------------------------------------------------------------------------
__global__ __launch_bounds__(256) void gemm2_mma(const float* __restrict__ bo,
                                                 const float* __restrict__ addt,
                                                 float* __restrict__ out) {
    __shared__ char sA[2 * TILE_B];
    __shared__ char sB[2 * TILE_B];
    const int bn = blockIdx.x, bm = blockIdx.y;
    const int lane = threadIdx.x & 31, wid = threadIdx.x >> 5;
    const int wm0 = (wid >> 1) * 32, wn0 = (wid & 1) * 64;

    float acc[2][8][4];
    gemm_core(g_ob + (size_t)bm * 128 * 256, g_wob + (size_t)bn * 128 * 256, sA, sB, acc);

    #pragma unroll
    for (int mt = 0; mt < 2; mt++) {
        #pragma unroll
        for (int nt = 0; nt < 8; nt++) {
            #pragma unroll
            for (int half = 0; half < 2; half++) {
                int m = bm * 128 + wm0 + mt * 16 + (lane >> 2) + half * 8;
                int c = bn * 128 + wn0 + nt * 8 + 2 * (lane & 3);
                int s = m >> 8, q = m & 255;
                size_t oi = ((size_t)q * 128 + s) * 256 + c;
                float2 a2 = *(const float2*)(addt + oi);
                float2 b2 = *(const float2*)(bo + c);
                float2 r2;
                r2.x = a2.x + b2.x + acc[mt][nt][2 * half];
                r2.y = a2.y + b2.y + acc[mt][nt][2 * half + 1];
                *(float2*)(out + oi) = r2;
            }
        }
    }
}

// ---------------------------------------------------------------------------
// Attention: single pass, packed f32x2 math. One block per (s,h).
// ---------------------------------------------------------------------------
__global__ __launch_bounds__(256) void attn(const float* __restrict__ mask) {
    extern __shared__ float smf[];
    float* ks = smf;            // [256][32] fp32
    float* vs = smf + 8192;
    float* madd = smf + 16384;  // [256]

    const int s = blockIdx.x >> 3;
    const int h = blockIdx.x & 7;
    const int t = threadIdx.x;

    const float4* kb = (const float4*)(g_k + (size_t)(s * 8 + h) * 256 * 32);
    const float4* vb = (const float4*)(g_v + (size_t)(s * 8 + h) * 256 * 32);
    for (int i = t; i < 2048; i += 256) {
        ((float4*)ks)[i] = kb[i];
        ((float4*)vs)[i] = vb[i];
    }
    madd[t] = (mask[s * 256 + t] - 1.0f) * 1e9f;
    __syncthreads();

    uint64_t q2[16];
    const ulonglong2* qb = (const ulonglong2*)(g_q + ((size_t)(s * 8 + h) * 256 + t) * 32);
    #pragma unroll
    for (int i = 0; i < 8; i++) { ulonglong2 p = qb[i]; q2[2 * i] = p.x; q2[2 * i + 1] = p.y; }

    uint64_t o2[16];
    #pragma unroll
    for (int i = 0; i < 16; i++) o2[i] = 0ull;
    float l = 0.f;
    const float* bt = g_biast + (size_t)h * 256 * 256 + t;

    for (int j = 0; j < 256; j++) {
        uint64_t acc = 0ull;
        const ulonglong2* kp = (const ulonglong2*)(ks + j * 32);
        #pragma unroll
        for (int i = 0; i < 8; i++) {
            ulonglong2 p = kp[i];
            fma2(acc, q2[2 * i], p.x);
            fma2(acc, q2[2 * i + 1], p.y);
        }
        float dlo = __uint_as_float((uint32_t)acc);
        float dhi = __uint_as_float((uint32_t)(acc >> 32));
        float logit = dlo + dhi + bt[j * 256] + madd[j];
        float w = __expf(fminf(logit, 80.f));
        l += w;
        uint64_t w2;
        asm("mov.b64 %0, {%1, %1};" : "=l"(w2) : "r"(__float_as_uint(w)));
        const ulonglong2* vp = (const ulonglong2*)(vs + j * 32);
        #pragma unroll
        for (int i = 0; i < 8; i++) {
            ulonglong2 p = vp[i];
            fma2(o2[2 * i], w2, p.x);
            fma2(o2[2 * i + 1], w2, p.y);
        }
    }

    float inv = 1.0f / l;
    int row = s * 256 + t;
    const float* gp = g_gate + (size_t)row * 256 + h * 32;
    uint32_t* op = (uint32_t*)(g_ob + (size_t)row * 256 + h * 32);
    #pragma unroll
    for (int i = 0; i < 16; i++) {
        float lo = __uint_as_float((uint32_t)o2[i]) * inv * gp[2 * i];
        float hi = __uint_as_float((uint32_t)(o2[i] >> 32)) * inv * gp[2 * i + 1];
        uint32_t pk;
        asm("cvt.rn.satfinite.bf16x2.f32 %0, %1, %2;" : "=r"(pk) : "f"(hi), "f"(lo));
        op[i] = pk;
    }
}

// ---------------------------------------------------------------------------
extern "C" void kernel_launch(void* const* d_in, const int* in_sizes, int n_in,
                              void* d_out, int out_size) {
    const float* x    = (const float*)d_in[0];
    const float* mask = (const float*)d_in[1];
    const float* bias = (const float*)d_in[2];
    const float* addt = (const float*)d_in[3];
    const float* wq   = (const float*)d_in[4];
    const float* wk   = (const float*)d_in[5];
    const float* wv   = (const float*)d_in[6];
    const float* wg   = (const float*)d_in[7];
    const float* bg   = (const float*)d_in[8];
    const float* wo   = (const float*)d_in[9];
    const float* bo   = (const float*)d_in[10];
    float* out = (float*)d_out;

    cudaFuncSetAttribute(attn, cudaFuncAttributeMaxDynamicSharedMemorySize, 66560);

    conv_x<<<(MROWS * 256 / 4 + 255) / 256, 256>>>(x);
    pack_w<<<1280, 256>>>(wq, wk, wv, wg, wo);
    bias_tr<<<dim3(8, 8, 8), dim3(32, 32)>>>(bias);

    gemm1_mma<<<dim3(8, 256), 256>>>(bg);
    attn<<<1024, 256, 66560>>>(mask);
    gemm2_mma<<<dim3(2, 256), 256>>>(bo, addt, out);
}

// round 7
// speedup vs baseline: 10.8830x; 2.1964x over previous
#include <cuda_runtime.h>
#include <cuda_bf16.h>
#include <cstdint>
#include <math.h>

#define SS 128
#define QQ 256
#define CC 256
#define HH 8
#define CHD 32
#define MROWS (SS*QQ)

// ---------------------------------------------------------------------------
// Helpers
// ---------------------------------------------------------------------------
__device__ __forceinline__ uint32_t smem_u32(const void* p) {
    uint32_t a;
    asm("{ .reg .u64 t; cvta.to.shared.u64 t, %1; cvt.u32.u64 %0, t; }" : "=r"(a) : "l"(p));
    return a;
}
__device__ __forceinline__ void cp16(uint32_t dst, const void* src) {
    asm volatile("cp.async.cg.shared.global [%0], [%1], 16;" :: "r"(dst), "l"(src));
}
__device__ __forceinline__ void ldmx4(uint32_t* f, uint32_t addr) {
    asm volatile("ldmatrix.sync.aligned.m8n8.x4.shared.b16 {%0,%1,%2,%3}, [%4];"
                 : "=r"(f[0]), "=r"(f[1]), "=r"(f[2]), "=r"(f[3]) : "r"(addr));
}
__device__ __forceinline__ void mma16816(float* c, const uint32_t* a, uint32_t b0, uint32_t b1) {
    asm volatile("mma.sync.aligned.m16n8k16.row.col.f32.bf16.bf16.f32 "
                 "{%0,%1,%2,%3}, {%4,%5,%6,%7}, {%8,%9}, {%0,%1,%2,%3};"
                 : "+f"(c[0]), "+f"(c[1]), "+f"(c[2]), "+f"(c[3])
                 : "r"(a[0]), "r"(a[1]), "r"(a[2]), "r"(a[3]), "r"(b0), "r"(b1));
}
__device__ __forceinline__ uint32_t packbf(float hi, float lo) {
    uint32_t pk;
    asm("cvt.rn.satfinite.bf16x2.f32 %0, %1, %2;" : "=r"(pk) : "f"(hi), "f"(lo));
    return pk;
}

// ---------------------------------------------------------------------------
// Scratch (device globals: allocation-free rule)
// ---------------------------------------------------------------------------
__device__ __nv_bfloat16 g_xb[MROWS * 256];       // input in bf16
__device__ __nv_bfloat16 g_wb[1024 * 256];        // packed wq|wk|wv|wg (wq pre-scaled)
__device__ __nv_bfloat16 g_wob[256 * 256];        // wo in bf16
__device__ __nv_bfloat16 g_qb[SS * HH * QQ * CHD]; // [s,h,q,d] bf16
__device__ __nv_bfloat16 g_kb[SS * HH * QQ * CHD];
__device__ __nv_bfloat16 g_vb[SS * HH * QQ * CHD];
__device__ float g_gate[MROWS * 256];             // sigmoid gate, [row, e]
__device__ __nv_bfloat16 g_ob[MROWS * 256];       // gated attention output (bf16)

// ---------------------------------------------------------------------------
// Prologue conversions
// ---------------------------------------------------------------------------
__global__ void conv_x(const float* __restrict__ x) {
    int i = blockIdx.x * blockDim.x + threadIdx.x;  // per 4 elements
    float4 v = ((const float4*)x)[i];
    __nv_bfloat162* dst = (__nv_bfloat162*)g_xb;
    dst[2 * i]     = __floats2bfloat162_rn(v.x, v.y);
    dst[2 * i + 1] = __floats2bfloat162_rn(v.z, v.w);
}

__global__ void pack_w(const float* __restrict__ wq, const float* __restrict__ wk,
                       const float* __restrict__ wv, const float* __restrict__ wg,
                       const float* __restrict__ wo) {
    int e = blockIdx.x;
    int c = threadIdx.x;
    if (e < 1024) {
        float val;
        if (e < 256)      val = wq[e * 256 + c] * 0.17677669529663687f;
        else if (e < 512) val = wk[(e - 256) * 256 + c];
        else if (e < 768) val = wv[(e - 512) * 256 + c];
        else              val = wg[(e - 768) * 256 + c];
        g_wb[e * 256 + c] = __float2bfloat16(val);
    } else {
        int r = e - 1024;
        g_wob[r * 256 + c] = __float2bfloat16(wo[r * 256 + c]);
    }
}

// ---------------------------------------------------------------------------
// Shared GEMM core (validated R6): C[128,128] = A[128,256] x B[128,256]^T
// ---------------------------------------------------------------------------
#define TILE_B 10240   // 128 rows * 80 bytes

__device__ __forceinline__ void gemm_core(const __nv_bfloat16* __restrict__ gA,
                                          const __nv_bfloat16* __restrict__ gB,
                                          char* sA, char* sB,
                                          float acc[2][8][4]) {
    const int tid = threadIdx.x, lane = tid & 31, wid = tid >> 5;
    const int wm0 = (wid >> 1) * 32, wn0 = (wid & 1) * 64;
    const uint32_t aB = smem_u32(sA), bB = smem_u32(sB);

    #pragma unroll
    for (int mt = 0; mt < 2; mt++)
        #pragma unroll
        for (int nt = 0; nt < 8; nt++)
            #pragma unroll
            for (int i = 0; i < 4; i++) acc[mt][nt][i] = 0.f;

    auto load_tile = [&](int buf, int k0) {
        #pragma unroll
        for (int j = 0; j < 2; j++) {
            int idx = tid + j * 256;
            int r = idx >> 2, ch = idx & 3;
            uint32_t so = (uint32_t)(buf * TILE_B + r * 80 + ch * 16);
            cp16(aB + so, gA + r * 256 + k0 + ch * 8);
            cp16(bB + so, gB + r * 256 + k0 + ch * 8);
        }
        asm volatile("cp.async.commit_group;" ::: "memory");
    };

    load_tile(0, 0);
    for (int kit = 0; kit < 8; kit++) {
        if (kit < 7) {
            load_tile((kit + 1) & 1, (kit + 1) * 32);
            asm volatile("cp.async.wait_group 1;" ::: "memory");
        } else {
            asm volatile("cp.async.wait_group 0;" ::: "memory");
        }
        __syncthreads();
        const uint32_t ab = aB + (kit & 1) * TILE_B;
        const uint32_t bb = bB + (kit & 1) * TILE_B;
        #pragma unroll
        for (int kk = 0; kk < 2; kk++) {
            uint32_t af[2][4];
            #pragma unroll
            for (int mt = 0; mt < 2; mt++) {
                int row = wm0 + mt * 16 + (lane & 15);
                int col = kk * 16 + ((lane >> 4) << 3);
                ldmx4(af[mt], ab + row * 80 + col * 2);
            }
            #pragma unroll
            for (int nt2 = 0; nt2 < 4; nt2++) {
                uint32_t bf[4];
                int nrow = wn0 + nt2 * 16 + (lane & 7) + ((lane >> 4) << 3);
                int ncol = kk * 16 + (((lane >> 3) & 1) << 3);
                ldmx4(bf, bb + nrow * 80 + ncol * 2);
                #pragma unroll
                for (int mt = 0; mt < 2; mt++) {
                    mma16816(acc[mt][2 * nt2],     af[mt], bf[0], bf[1]);
                    mma16816(acc[mt][2 * nt2 + 1], af[mt], bf[2], bf[3]);
                }
            }
        }
        __syncthreads();
    }
}

// ---------------------------------------------------------------------------
// GEMM1: Y[32768,1024] = Xb @ Wb^T. Epilogue: q/k/v in bf16 + sigmoid gate.
// ---------------------------------------------------------------------------
__global__ __launch_bounds__(256) void gemm1_mma(const float* __restrict__ bg) {
    __shared__ char sA[2 * TILE_B];
    __shared__ char sB[2 * TILE_B];
    const int bn = blockIdx.x, bm = blockIdx.y;
    const int lane = threadIdx.x & 31, wid = threadIdx.x >> 5;
    const int wm0 = (wid >> 1) * 32, wn0 = (wid & 1) * 64;

    float acc[2][8][4];
    gemm_core(g_xb + (size_t)bm * 128 * 256, g_wb + (size_t)bn * 128 * 256, sA, sB, acc);

    #pragma unroll
    for (int mt = 0; mt < 2; mt++) {
        #pragma unroll
        for (int nt = 0; nt < 8; nt++) {
            #pragma unroll
            for (int half = 0; half < 2; half++) {
                int m = bm * 128 + wm0 + mt * 16 + (lane >> 2) + half * 8;
                int e = bn * 128 + wn0 + nt * 8 + 2 * (lane & 3);
                float v0 = acc[mt][nt][2 * half];
                float v1 = acc[mt][nt][2 * half + 1];
                int s = m >> 8, q = m & 255;
                if (e < 768) {
                    int which = e >> 8;
                    int h = (e >> 5) & 7;
                    int d = e & 31;
                    __nv_bfloat16* dst = (which == 0 ? g_qb : (which == 1 ? g_kb : g_vb)) +
                                         ((size_t)(s * 8 + h) * 256 + q) * 32 + d;
                    *(uint32_t*)dst = packbf(v1, v0);
                } else {
                    int eg = e - 768;
                    float g0 = 1.0f / (1.0f + __expf(-(v0 + bg[eg])));
                    float g1 = 1.0f / (1.0f + __expf(-(v1 + bg[eg + 1])));
                    *(float2*)(g_gate + (size_t)m * 256 + eg) = make_float2(g0, g1);
                }
            }
        }
    }
}

// ---------------------------------------------------------------------------
// GEMM2: out[q,s,c] = addt + g_ob @ wo^T + bo. grid (2, 256)
// ---------------------------------------------------------------------------
__global__ __launch_bounds__(256) void gemm2_mma(const float* __restrict__ bo,
                                                 const float* __restrict__ addt,
                                                 float* __restrict__ out) {
    __shared__ char sA[2 * TILE_B];
    __shared__ char sB[2 * TILE_B];
    const int bn = blockIdx.x, bm = blockIdx.y;
    const int lane = threadIdx.x & 31, wid = threadIdx.x >> 5;
    const int wm0 = (wid >> 1) * 32, wn0 = (wid & 1) * 64;

    float acc[2][8][4];
    gemm_core(g_ob + (size_t)bm * 128 * 256, g_wob + (size_t)bn * 128 * 256, sA, sB, acc);

    #pragma unroll
    for (int mt = 0; mt < 2; mt++) {
        #pragma unroll
        for (int nt = 0; nt < 8; nt++) {
            #pragma unroll
            for (int half = 0; half < 2; half++) {
                int m = bm * 128 + wm0 + mt * 16 + (lane >> 2) + half * 8;
                int c = bn * 128 + wn0 + nt * 8 + 2 * (lane & 3);
                int s = m >> 8, q = m & 255;
                size_t oi = ((size_t)q * 128 + s) * 256 + c;
                float2 a2 = *(const float2*)(addt + oi);
                float2 b2 = *(const float2*)(bo + c);
                float2 r2;
                r2.x = a2.x + b2.x + acc[mt][nt][2 * half];
                r2.y = a2.y + b2.y + acc[mt][nt][2 * half + 1];
                *(float2*)(out + oi) = r2;
            }
        }
    }
}

// ---------------------------------------------------------------------------
// Tensor-core flash attention. One CTA per (s,h), 8 warps x 32 q-rows.
// S = Q K^T via mma (bf16), +bias+mask, exp, P->A fragment, O += P V via mma.
// ---------------------------------------------------------------------------
#define QS_OFF   0         // 256 rows x 80B
#define KS_OFF   20480     // 256 rows x 80B
#define VT_OFF   40960     // Vt: 32 rows x 528B
#define MADD_OFF 57856     // 256 floats
#define ATTN_SMEM 58880

__global__ __launch_bounds__(256) void attn_tc(const float* __restrict__ bias,
                                               const float* __restrict__ mask) {
    extern __shared__ char smp[];
    const uint32_t sb = smem_u32(smp);
    const int s = blockIdx.x >> 3;
    const int h = blockIdx.x & 7;
    const int t = threadIdx.x;
    const int lane = t & 31, w = t >> 5;

    const size_t hb = (size_t)(s * 8 + h) * 16384;   // byte offset of this (s,h) tile

    // cp.async Q, K tiles into 80B-pitch smem
    #pragma unroll
    for (int j = 0; j < 4; j++) {
        int idx = t + j * 256;
        int r = idx >> 2, ch = idx & 3;
        cp16(sb + QS_OFF + r * 80 + ch * 16, (const char*)g_qb + hb + r * 64 + ch * 16);
        cp16(sb + KS_OFF + r * 80 + ch * 16, (const char*)g_kb + hb + r * 64 + ch * 16);
    }
    asm volatile("cp.async.commit_group;" ::: "memory");

    // V transpose: thread t reads V row k=t (32 bf16), scatters to Vt[d][k=t]
    {
        union { uint4 v4[4]; uint16_t u16[32]; } tv;
        const uint4* vr = (const uint4*)((const char*)g_vb + hb + t * 64);
        tv.v4[0] = vr[0]; tv.v4[1] = vr[1]; tv.v4[2] = vr[2]; tv.v4[3] = vr[3];
        #pragma unroll
        for (int d = 0; d < 32; d++)
            *(uint16_t*)(smp + VT_OFF + d * 528 + 2 * t) = tv.u16[d];
    }
    // mask additive term
    *(float*)(smp + MADD_OFF + 4 * t) = (mask[s * 256 + t] - 1.0f) * 1e9f;

    asm volatile("cp.async.wait_group 0;" ::: "memory");
    __syncthreads();

    // Q fragments for this warp's 32 rows
    uint32_t af[2][2][4];   // [mt][kstep]
    #pragma unroll
    for (int mt = 0; mt < 2; mt++)
        #pragma unroll
        for (int ks = 0; ks < 2; ks++) {
            int row = 32 * w + mt * 16 + (lane & 15);
            int col = ks * 16 + ((lane >> 4) << 3);
            ldmx4(af[mt][ks], sb + QS_OFF + row * 80 + col * 2);
        }

    float o_acc[2][4][4];
    #pragma unroll
    for (int mt = 0; mt < 2; mt++)
        #pragma unroll
        for (int nt = 0; nt < 4; nt++)
            #pragma unroll
            for (int i = 0; i < 4; i++) o_acc[mt][nt][i] = 0.f;
    float lsum[2][2] = {};

    const int r_lo = (lane >> 2);         // row-in-tile for c0,c1
    const int jo   = 2 * (lane & 3);      // col pair offset

    for (int c = 0; c < 8; c++) {
        // ---- S = Q K^T for this 32-key chunk ----
        float s_acc[2][4][4];
        #pragma unroll
        for (int mt = 0; mt < 2; mt++)
            #pragma unroll
            for (int nt = 0; nt < 4; nt++)
                #pragma unroll
                for (int i = 0; i < 4; i++) s_acc[mt][nt][i] = 0.f;

        #pragma unroll
        for (int ks = 0; ks < 2; ks++) {
            #pragma unroll
            for (int nt2 = 0; nt2 < 2; nt2++) {
                uint32_t bf[4];
                int nrow = c * 32 + nt2 * 16 + (lane & 7) + ((lane >> 4) << 3);
                int ncol = ks * 16 + (((lane >> 3) & 1) << 3);
                ldmx4(bf, sb + KS_OFF + nrow * 80 + ncol * 2);
                #pragma unroll
                for (int mt = 0; mt < 2; mt++) {
                    mma16816(s_acc[mt][2 * nt2],     af[mt][ks], bf[0], bf[1]);
                    mma16816(s_acc[mt][2 * nt2 + 1], af[mt][ks], bf[2], bf[3]);
                }
            }
        }

        // ---- bias + mask, exp, pack P fragments ----
        uint32_t pfrag[2][4][2];
        #pragma unroll
        for (int mt = 0; mt < 2; mt++) {
            int r0 = 32 * w + mt * 16 + r_lo;
            #pragma unroll
            for (int nt = 0; nt < 4; nt++) {
                int j = c * 32 + nt * 8 + jo;
                float2 mj = *(const float2*)(smp + MADD_OFF + 4 * j);
                float2 b0 = *(const float2*)(bias + ((size_t)(h * 256 + r0) * 256 + j));
                float2 b1 = *(const float2*)(bias + ((size_t)(h * 256 + r0 + 8) * 256 + j));
                float w00 = __expf(fminf(s_acc[mt][nt][0] + b0.x + mj.x, 80.f));
                float w01 = __expf(fminf(s_acc[mt][nt][1] + b0.y + mj.y, 80.f));
                float w10 = __expf(fminf(s_acc[mt][nt][2] + b1.x + mj.x, 80.f));
                float w11 = __expf(fminf(s_acc[mt][nt][3] + b1.y + mj.y, 80.f));
                lsum[mt][0] += w00 + w01;
                lsum[mt][1] += w10 + w11;
                pfrag[mt][nt][0] = packbf(w01, w00);
                pfrag[mt][nt][1] = packbf(w11, w10);
            }
        }

        // ---- O += P V ----
        #pragma unroll
        for (int ks2 = 0; ks2 < 2; ks2++) {
            uint32_t bv[2][4];
            #pragma unroll
            for (int nv = 0; nv < 2; nv++) {
                int nrow = nv * 16 + (lane & 7) + ((lane >> 4) << 3);
                int ncol = c * 32 + ks2 * 16 + (((lane >> 3) & 1) << 3);
                ldmx4(bv[nv], sb + VT_OFF + nrow * 528 + ncol * 2);
            }
            #pragma unroll
            for (int mt = 0; mt < 2; mt++) {
                uint32_t aP[4] = { pfrag[mt][2 * ks2][0], pfrag[mt][2 * ks2][1],
                                   pfrag[mt][2 * ks2 + 1][0], pfrag[mt][2 * ks2 + 1][1] };
                #pragma unroll
                for (int nv = 0; nv < 2; nv++) {
                    mma16816(o_acc[mt][2 * nv],     aP, bv[nv][0], bv[nv][1]);
                    mma16816(o_acc[mt][2 * nv + 1], aP, bv[nv][2], bv[nv][3]);
                }
            }
        }
    }

    // ---- row-sum reduce + normalize + gate + store ----
    float inv[2][2];
    #pragma unroll
    for (int mt = 0; mt < 2; mt++)
        #pragma unroll
        for (int half = 0; half < 2; half++) {
            float lv = lsum[mt][half];
            lv += __shfl_xor_sync(0xffffffffu, lv, 1);
            lv += __shfl_xor_sync(0xffffffffu, lv, 2);
            inv[mt][half] = 1.0f / lv;
        }

    #pragma unroll
    for (int mt = 0; mt < 2; mt++) {
        int q0 = 32 * w + mt * 16 + r_lo;
        int row0 = s * 256 + q0;
        #pragma unroll
        for (int nv = 0; nv < 4; nv++) {
            int d = nv * 8 + jo;
            float2 ga = *(const float2*)(g_gate + (size_t)row0 * 256 + h * 32 + d);
            float2 gb = *(const float2*)(g_gate + (size_t)(row0 + 8) * 256 + h * 32 + d);
            float v00 = o_acc[mt][nv][0] * inv[mt][0] * ga.x;
            float v01 = o_acc[mt][nv][1] * inv[mt][0] * ga.y;
            float v10 = o_acc[mt][nv][2] * inv[mt][1] * gb.x;
            float v11 = o_acc[mt][nv][3] * inv[mt][1] * gb.y;
            *(uint32_t*)(g_ob + (size_t)row0 * 256 + h * 32 + d) = packbf(v01, v00);
            *(uint32_t*)(g_ob + (size_t)(row0 + 8) * 256 + h * 32 + d) = packbf(v11, v10);
        }
    }
}

// ---------------------------------------------------------------------------
extern "C" void kernel_launch(void* const* d_in, const int* in_sizes, int n_in,
                              void* d_out, int out_size) {
    const float* x    = (const float*)d_in[0];
    const float* mask = (const float*)d_in[1];
    const float* bias = (const float*)d_in[2];
    const float* addt = (const float*)d_in[3];
    const float* wq   = (const float*)d_in[4];
    const float* wk   = (const float*)d_in[5];
    const float* wv   = (const float*)d_in[6];
    const float* wg   = (const float*)d_in[7];
    const float* bg   = (const float*)d_in[8];
    const float* wo   = (const float*)d_in[9];
    const float* bo   = (const float*)d_in[10];
    float* out = (float*)d_out;

    cudaFuncSetAttribute(attn_tc, cudaFuncAttributeMaxDynamicSharedMemorySize, ATTN_SMEM);

    conv_x<<<(MROWS * 256 / 4 + 255) / 256, 256>>>(x);
    pack_w<<<1280, 256>>>(wq, wk, wv, wg, wo);

    gemm1_mma<<<dim3(8, 256), 256>>>(bg);
    attn_tc<<<1024, 256, ATTN_SMEM>>>(bias, mask);
    gemm2_mma<<<dim3(2, 256), 256>>>(bo, addt, out);
}

// round 10
// speedup vs baseline: 11.1086x; 1.0207x over previous
#include <cuda_runtime.h>
#include <cuda_bf16.h>
#include <cstdint>
#include <math.h>

#define SS 128
#define QQ 256
#define CC 256
#define HH 8
#define CHD 32
#define MROWS (SS*QQ)

// ---------------------------------------------------------------------------
// Helpers
// ---------------------------------------------------------------------------
__device__ __forceinline__ uint32_t smem_u32(const void* p) {
    uint32_t a;
    asm("{ .reg .u64 t; cvta.to.shared.u64 t, %1; cvt.u32.u64 %0, t; }" : "=r"(a) : "l"(p));
    return a;
}
__device__ __forceinline__ void cp16(uint32_t dst, const void* src) {
    asm volatile("cp.async.cg.shared.global [%0], [%1], 16;" :: "r"(dst), "l"(src));
}
__device__ __forceinline__ void ldmx4(uint32_t* f, uint32_t addr) {
    asm volatile("ldmatrix.sync.aligned.m8n8.x4.shared.b16 {%0,%1,%2,%3}, [%4];"
                 : "=r"(f[0]), "=r"(f[1]), "=r"(f[2]), "=r"(f[3]) : "r"(addr));
}
__device__ __forceinline__ void mma16816(float* c, const uint32_t* a, uint32_t b0, uint32_t b1) {
    asm volatile("mma.sync.aligned.m16n8k16.row.col.f32.bf16.bf16.f32 "
                 "{%0,%1,%2,%3}, {%4,%5,%6,%7}, {%8,%9}, {%0,%1,%2,%3};"
                 : "+f"(c[0]), "+f"(c[1]), "+f"(c[2]), "+f"(c[3])
                 : "r"(a[0]), "r"(a[1]), "r"(a[2]), "r"(a[3]), "r"(b0), "r"(b1));
}
__device__ __forceinline__ uint32_t packbf(float hi, float lo) {
    uint32_t pk;
    asm("cvt.rn.satfinite.bf16x2.f32 %0, %1, %2;" : "=r"(pk) : "f"(hi), "f"(lo));
    return pk;
}

// ---------------------------------------------------------------------------
// Scratch (device globals: allocation-free rule)
// ---------------------------------------------------------------------------
__device__ __nv_bfloat16 g_xb[MROWS * 256];        // input in bf16
__device__ __nv_bfloat16 g_wb[1024 * 256];         // packed wq|wk|wv|wg (wq pre-scaled)
__device__ __nv_bfloat16 g_wob[256 * 256];         // wo in bf16
__device__ __nv_bfloat16 g_qb[SS * HH * QQ * CHD]; // [s,h,q,d] bf16
__device__ __nv_bfloat16 g_kb[SS * HH * QQ * CHD];
__device__ __nv_bfloat16 g_vb[SS * HH * QQ * CHD];
__device__ float g_gate[MROWS * 256];              // sigmoid gate, [row, e]
__device__ __nv_bfloat16 g_ob[MROWS * 256];        // gated attention output (bf16)
__device__ __nv_bfloat16 g_biasb[HH * QQ * QQ];    // bias in bf16

// ---------------------------------------------------------------------------
// Prologue conversions
// ---------------------------------------------------------------------------
__global__ void conv_x(const float* __restrict__ x) {
    int i = blockIdx.x * blockDim.x + threadIdx.x;  // per 4 elements
    float4 v = ((const float4*)x)[i];
    __nv_bfloat162* dst = (__nv_bfloat162*)g_xb;
    dst[2 * i]     = __floats2bfloat162_rn(v.x, v.y);
    dst[2 * i + 1] = __floats2bfloat162_rn(v.z, v.w);
}

__global__ void conv_bias(const float* __restrict__ bias) {
    int i = blockIdx.x * blockDim.x + threadIdx.x;  // per 4 elements
    float4 v = ((const float4*)bias)[i];
    __nv_bfloat162* dst = (__nv_bfloat162*)g_biasb;
    dst[2 * i]     = __floats2bfloat162_rn(v.x, v.y);
    dst[2 * i + 1] = __floats2bfloat162_rn(v.z, v.w);
}

__global__ void pack_w(const float* __restrict__ wq, const float* __restrict__ wk,
                       const float* __restrict__ wv, const float* __restrict__ wg,
                       const float* __restrict__ wo) {
    int e = blockIdx.x;
    int c = threadIdx.x;
    if (e < 1024) {
        float val;
        if (e < 256)      val = wq[e * 256 + c] * 0.17677669529663687f;
        else if (e < 512) val = wk[(e - 256) * 256 + c];
        else if (e < 768) val = wv[(e - 512) * 256 + c];
        else              val = wg[(e - 768) * 256 + c];
        g_wb[e * 256 + c] = __float2bfloat16(val);
    } else {
        int r = e - 1024;
        g_wob[r * 256 + c] = __float2bfloat16(wo[r * 256 + c]);
    }
}

// ---------------------------------------------------------------------------
// Shared GEMM core: C[128,128] = A[128,256] x B[128,256]^T (NT, bf16, f32 acc)
// 3-stage cp.async pipeline, ONE __syncthreads per K-iteration.
// Order per iter: wait(tile k) -> syncthreads (visibility + prev compute done)
//                 -> prefetch tile k+2 (into buf consumed at k-1) -> compute k
// ---------------------------------------------------------------------------
#define TILE_B 10240           // 128 rows * 80 bytes
#define GEMM_SMEM (6 * TILE_B) // 3 stages x 2 operands

__device__ __forceinline__ void gemm_core(const __nv_bfloat16* __restrict__ gA,
                                          const __nv_bfloat16* __restrict__ gB,
                                          char* sA, char* sB,
                                          float acc[2][8][4]) {
    const int tid = threadIdx.x, lane = tid & 31, wid = tid >> 5;
    const int wm0 = (wid >> 1) * 32, wn0 = (wid & 1) * 64;
    const uint32_t aB = smem_u32(sA), bB = smem_u32(sB);

    #pragma unroll
    for (int mt = 0; mt < 2; mt++)
        #pragma unroll
        for (int nt = 0; nt < 8; nt++)
            #pragma unroll
            for (int i = 0; i < 4; i++) acc[mt][nt][i] = 0.f;

    auto load_tile = [&](int buf, int k0) {
        #pragma unroll
        for (int j = 0; j < 2; j++) {
            int idx = tid + j * 256;
            int r = idx >> 2, ch = idx & 3;
            uint32_t so = (uint32_t)(buf * TILE_B + r * 80 + ch * 16);
            cp16(aB + so, gA + r * 256 + k0 + ch * 8);
            cp16(bB + so, gB + r * 256 + k0 + ch * 8);
        }
        asm volatile("cp.async.commit_group;" ::: "memory");
    };

    load_tile(0, 0);
    load_tile(1, 32);

    #pragma unroll
    for (int kit = 0; kit < 8; kit++) {
        if (kit < 7) {
            asm volatile("cp.async.wait_group 1;" ::: "memory");  // tile kit done (this thread)
        } else {
            asm volatile("cp.async.wait_group 0;" ::: "memory");
        }
        __syncthreads();   // all threads waited -> tile kit visible; compute kit-1 done
        if (kit < 6) {
            load_tile((kit + 2) % 3, (kit + 2) * 32);  // buf (kit+2)%3 == (kit-1)%3, free
        }
        const uint32_t ab = aB + (kit % 3) * TILE_B;
        const uint32_t bb = bB + (kit % 3) * TILE_B;
        #pragma unroll
        for (int kk = 0; kk < 2; kk++) {
            uint32_t af[2][4];
            #pragma unroll
            for (int mt = 0; mt < 2; mt++) {
                int row = wm0 + mt * 16 + (lane & 15);
                int col = kk * 16 + ((lane >> 4) << 3);
                ldmx4(af[mt], ab + row * 80 + col * 2);
            }
            #pragma unroll
            for (int nt2 = 0; nt2 < 4; nt2++) {
                uint32_t bf[4];
                int nrow = wn0 + nt2 * 16 + (lane & 7) + ((lane >> 4) << 3);
                int ncol = kk * 16 + (((lane >> 3) & 1) << 3);
                ldmx4(bf, bb + nrow * 80 + ncol * 2);
                #pragma unroll
                for (int mt = 0; mt < 2; mt++) {
                    mma16816(acc[mt][2 * nt2],     af[mt], bf[0], bf[1]);
                    mma16816(acc[mt][2 * nt2 + 1], af[mt], bf[2], bf[3]);
                }
            }
        }
    }
}

// ---------------------------------------------------------------------------
// GEMM1: Y[32768,1024] = Xb @ Wb^T. Epilogue: q/k/v in bf16 + sigmoid gate.
// ---------------------------------------------------------------------------
__global__ __launch_bounds__(256) void gemm1_mma(const float* __restrict__ bg) {
    extern __shared__ char dynsm[];
    char* sA = dynsm;
    char* sB = dynsm + 3 * TILE_B;
    const int bn = blockIdx.x, bm = blockIdx.y;
    const int lane = threadIdx.x & 31, wid = threadIdx.x >> 5;
    const int wm0 = (wid >> 1) * 32, wn0 = (wid & 1) * 64;

    float acc[2][8][4];
    gemm_core(g_xb + (size_t)bm * 128 * 256, g_wb + (size_t)bn * 128 * 256, sA, sB, acc);

    #pragma unroll
    for (int mt = 0; mt < 2; mt++) {
        #pragma unroll
        for (int nt = 0; nt < 8; nt++) {
            #pragma unroll
            for (int half = 0; half < 2; half++) {
                int m = bm * 128 + wm0 + mt * 16 + (lane >> 2) + half * 8;
                int e = bn * 128 + wn0 + nt * 8 + 2 * (lane & 3);
                float v0 = acc[mt][nt][2 * half];
                float v1 = acc[mt][nt][2 * half + 1];
                int s = m >> 8, q = m & 255;
                if (e < 768) {
                    int which = e >> 8;
                    int h = (e >> 5) & 7;
                    int d = e & 31;
                    __nv_bfloat16* dst = (which == 0 ? g_qb : (which == 1 ? g_kb : g_vb)) +
                                         ((size_t)(s * 8 + h) * 256 + q) * 32 + d;
                    *(uint32_t*)dst = packbf(v1, v0);
                } else {
                    int eg = e - 768;
                    float g0 = 1.0f / (1.0f + __expf(-(v0 + bg[eg])));
                    float g1 = 1.0f / (1.0f + __expf(-(v1 + bg[eg + 1])));
                    *(float2*)(g_gate + (size_t)m * 256 + eg) = make_float2(g0, g1);
                }
            }
        }
    }
}

// ---------------------------------------------------------------------------
// GEMM2: out[q,s,c] = addt + g_ob @ wo^T + bo. grid (2, 256)
// ---------------------------------------------------------------------------
__global__ __launch_bounds__(256) void gemm2_mma(const float* __restrict__ bo,
                                                 const float* __restrict__ addt,
                                                 float* __restrict__ out) {
    extern __shared__ char dynsm[];
    char* sA = dynsm;
    char* sB = dynsm + 3 * TILE_B;
    const int bn = blockIdx.x, bm = blockIdx.y;
    const int lane = threadIdx.x & 31, wid = threadIdx.x >> 5;
    const int wm0 = (wid >> 1) * 32, wn0 = (wid & 1) * 64;

    float acc[2][8][4];
    gemm_core(g_ob + (size_t)bm * 128 * 256, g_wob + (size_t)bn * 128 * 256, sA, sB, acc);

    #pragma unroll
    for (int mt = 0; mt < 2; mt++) {
        #pragma unroll
        for (int nt = 0; nt < 8; nt++) {
            #pragma unroll
            for (int half = 0; half < 2; half++) {
                int m = bm * 128 + wm0 + mt * 16 + (lane >> 2) + half * 8;
                int c = bn * 128 + wn0 + nt * 8 + 2 * (lane & 3);
                int s = m >> 8, q = m & 255;
                size_t oi = ((size_t)q * 128 + s) * 256 + c;
                float2 a2 = *(const float2*)(addt + oi);
                float2 b2 = *(const float2*)(bo + c);
                float2 r2;
                r2.x = a2.x + b2.x + acc[mt][nt][2 * half];
                r2.y = a2.y + b2.y + acc[mt][nt][2 * half + 1];
                *(float2*)(out + oi) = r2;
            }
        }
    }
}

// ---------------------------------------------------------------------------
// Tensor-core flash attention. One CTA per (s,h), 8 warps x 32 q-rows.
// ---------------------------------------------------------------------------
#define QS_OFF   0         // 256 rows x 80B
#define KS_OFF   20480     // 256 rows x 80B
#define VT_OFF   40960     // Vt: 32 rows x 528B
#define MADD_OFF 57856     // 256 floats
#define ATTN_SMEM 58880

__global__ __launch_bounds__(256) void attn_tc(const float* __restrict__ mask) {
    extern __shared__ char smp[];
    const uint32_t sb = smem_u32(smp);
    const int s = blockIdx.x >> 3;
    const int h = blockIdx.x & 7;
    const int t = threadIdx.x;
    const int lane = t & 31, w = t >> 5;

    const size_t hb = (size_t)(s * 8 + h) * 16384;   // byte offset of this (s,h) tile

    // cp.async Q, K tiles into 80B-pitch smem
    #pragma unroll
    for (int j = 0; j < 4; j++) {
        int idx = t + j * 256;
        int r = idx >> 2, ch = idx & 3;
        cp16(sb + QS_OFF + r * 80 + ch * 16, (const char*)g_qb + hb + r * 64 + ch * 16);
        cp16(sb + KS_OFF + r * 80 + ch * 16, (const char*)g_kb + hb + r * 64 + ch * 16);
    }
    asm volatile("cp.async.commit_group;" ::: "memory");

    // V transpose: thread t reads V row k=t (32 bf16), scatters to Vt[d][k=t]
    {
        union { uint4 v4[4]; uint16_t u16[32]; } tv;
        const uint4* vr = (const uint4*)((const char*)g_vb + hb + t * 64);
        tv.v4[0] = vr[0]; tv.v4[1] = vr[1]; tv.v4[2] = vr[2]; tv.v4[3] = vr[3];
        #pragma unroll
        for (int d = 0; d < 32; d++)
            *(uint16_t*)(smp + VT_OFF + d * 528 + 2 * t) = tv.u16[d];
    }
    // mask additive term
    *(float*)(smp + MADD_OFF + 4 * t) = (mask[s * 256 + t] - 1.0f) * 1e9f;

    asm volatile("cp.async.wait_group 0;" ::: "memory");
    __syncthreads();

    // Q fragments for this warp's 32 rows
    uint32_t af[2][2][4];   // [mt][kstep]
    #pragma unroll
    for (int mt = 0; mt < 2; mt++)
        #pragma unroll
        for (int ks = 0; ks < 2; ks++) {
            int row = 32 * w + mt * 16 + (lane & 15);
            int col = ks * 16 + ((lane >> 4) << 3);
            ldmx4(af[mt][ks], sb + QS_OFF + row * 80 + col * 2);
        }

    float o_acc[2][4][4];
    #pragma unroll
    for (int mt = 0; mt < 2; mt++)
        #pragma unroll
        for (int nt = 0; nt < 4; nt++)
            #pragma unroll
            for (int i = 0; i < 4; i++) o_acc[mt][nt][i] = 0.f;
    float lsum[2][2] = {};

    const int r_lo = (lane >> 2);         // row-in-tile for c0,c1
    const int jo   = 2 * (lane & 3);      // col pair offset

    for (int c = 0; c < 8; c++) {
        // ---- S = Q K^T for this 32-key chunk ----
        float s_acc[2][4][4];
        #pragma unroll
        for (int mt = 0; mt < 2; mt++)
            #pragma unroll
            for (int nt = 0; nt < 4; nt++)
                #pragma unroll
                for (int i = 0; i < 4; i++) s_acc[mt][nt][i] = 0.f;

        #pragma unroll
        for (int ks = 0; ks < 2; ks++) {
            #pragma unroll
            for (int nt2 = 0; nt2 < 2; nt2++) {
                uint32_t bf[4];
                int nrow = c * 32 + nt2 * 16 + (lane & 7) + ((lane >> 4) << 3);
                int ncol = ks * 16 + (((lane >> 3) & 1) << 3);
                ldmx4(bf, sb + KS_OFF + nrow * 80 + ncol * 2);
                #pragma unroll
                for (int mt = 0; mt < 2; mt++) {
                    mma16816(s_acc[mt][2 * nt2],     af[mt][ks], bf[0], bf[1]);
                    mma16816(s_acc[mt][2 * nt2 + 1], af[mt][ks], bf[2], bf[3]);
                }
            }
        }

        // ---- bias(bf16) + mask, exp, pack P fragments ----
        uint32_t pfrag[2][4][2];
        #pragma unroll
        for (int mt = 0; mt < 2; mt++) {
            int r0 = 32 * w + mt * 16 + r_lo;
            #pragma unroll
            for (int nt = 0; nt < 4; nt++) {
                int j = c * 32 + nt * 8 + jo;
                float2 mj = *(const float2*)(smp + MADD_OFF + 4 * j);
                __nv_bfloat162 bb0 = *(const __nv_bfloat162*)(g_biasb + ((size_t)(h * 256 + r0) * 256 + j));
                __nv_bfloat162 bb1 = *(const __nv_bfloat162*)(g_biasb + ((size_t)(h * 256 + r0 + 8) * 256 + j));
                float2 b0 = __bfloat1622float2(bb0);
                float2 b1 = __bfloat1622float2(bb1);
                float w00 = __expf(fminf(s_acc[mt][nt][0] + b0.x + mj.x, 80.f));
                float w01 = __expf(fminf(s_acc[mt][nt][1] + b0.y + mj.y, 80.f));
                float w10 = __expf(fminf(s_acc[mt][nt][2] + b1.x + mj.x, 80.f));
                float w11 = __expf(fminf(s_acc[mt][nt][3] + b1.y + mj.y, 80.f));
                lsum[mt][0] += w00 + w01;
                lsum[mt][1] += w10 + w11;
                pfrag[mt][nt][0] = packbf(w01, w00);
                pfrag[mt][nt][1] = packbf(w11, w10);
            }
        }

        // ---- O += P V ----
        #pragma unroll
        for (int ks2 = 0; ks2 < 2; ks2++) {
            uint32_t bv[2][4];
            #pragma unroll
            for (int nv = 0; nv < 2; nv++) {
                int nrow = nv * 16 + (lane & 7) + ((lane >> 4) << 3);
                int ncol = c * 32 + ks2 * 16 + (((lane >> 3) & 1) << 3);
                ldmx4(bv[nv], sb + VT_OFF + nrow * 528 + ncol * 2);
            }
            #pragma unroll
            for (int mt = 0; mt < 2; mt++) {
                uint32_t aP[4] = { pfrag[mt][2 * ks2][0], pfrag[mt][2 * ks2][1],
                                   pfrag[mt][2 * ks2 + 1][0], pfrag[mt][2 * ks2 + 1][1] };
                #pragma unroll
                for (int nv = 0; nv < 2; nv++) {
                    mma16816(o_acc[mt][2 * nv],     aP, bv[nv][0], bv[nv][1]);
                    mma16816(o_acc[mt][2 * nv + 1], aP, bv[nv][2], bv[nv][3]);
                }
            }
        }
    }

    // ---- row-sum reduce + normalize + gate + store ----
    float inv[2][2];
    #pragma unroll
    for (int mt = 0; mt < 2; mt++)
        #pragma unroll
        for (int half = 0; half < 2; half++) {
            float lv = lsum[mt][half];
            lv += __shfl_xor_sync(0xffffffffu, lv, 1);
            lv += __shfl_xor_sync(0xffffffffu, lv, 2);
            inv[mt][half] = 1.0f / lv;
        }

    #pragma unroll
    for (int mt = 0; mt < 2; mt++) {
        int q0 = 32 * w + mt * 16 + r_lo;
        int row0 = s * 256 + q0;
        #pragma unroll
        for (int nv = 0; nv < 4; nv++) {
            int d = nv * 8 + jo;
            float2 ga = *(const float2*)(g_gate + (size_t)row0 * 256 + h * 32 + d);
            float2 gb = *(const float2*)(g_gate + (size_t)(row0 + 8) * 256 + h * 32 + d);
            float v00 = o_acc[mt][nv][0] * inv[mt][0] * ga.x;
            float v01 = o_acc[mt][nv][1] * inv[mt][0] * ga.y;
            float v10 = o_acc[mt][nv][2] * inv[mt][1] * gb.x;
            float v11 = o_acc[mt][nv][3] * inv[mt][1] * gb.y;
            *(uint32_t*)(g_ob + (size_t)row0 * 256 + h * 32 + d) = packbf(v01, v00);
            *(uint32_t*)(g_ob + (size_t)(row0 + 8) * 256 + h * 32 + d) = packbf(v11, v10);
        }
    }
}

// ---------------------------------------------------------------------------
extern "C" void kernel_launch(void* const* d_in, const int* in_sizes, int n_in,
                              void* d_out, int out_size) {
    const float* x    = (const float*)d_in[0];
    const float* mask = (const float*)d_in[1];
    const float* bias = (const float*)d_in[2];
    const float* addt = (const float*)d_in[3];
    const float* wq   = (const float*)d_in[4];
    const float* wk   = (const float*)d_in[5];
    const float* wv   = (const float*)d_in[6];
    const float* wg   = (const float*)d_in[7];
    const float* bg   = (const float*)d_in[8];
    const float* wo   = (const float*)d_in[9];
    const float* bo   = (const float*)d_in[10];
    float* out = (float*)d_out;

    cudaFuncSetAttribute(attn_tc, cudaFuncAttributeMaxDynamicSharedMemorySize, ATTN_SMEM);
    cudaFuncSetAttribute(gemm1_mma, cudaFuncAttributeMaxDynamicSharedMemorySize, GEMM_SMEM);
    cudaFuncSetAttribute(gemm2_mma, cudaFuncAttributeMaxDynamicSharedMemorySize, GEMM_SMEM);

    conv_x<<<(MROWS * 256 / 4 + 255) / 256, 256>>>(x);
    conv_bias<<<(HH * QQ * QQ / 4 + 255) / 256, 256>>>(bias);
    pack_w<<<1280, 256>>>(wq, wk, wv, wg, wo);

    gemm1_mma<<<dim3(8, 256), 256, GEMM_SMEM>>>(bg);
    attn_tc<<<1024, 256, ATTN_SMEM>>>(mask);
    gemm2_mma<<<dim3(2, 256), 256, GEMM_SMEM>>>(bo, addt, out);
}

// round 11
// speedup vs baseline: 11.1103x; 1.0002x over previous
#include <cuda_runtime.h>
#include <cuda_bf16.h>
#include <cstdint>
#include <math.h>

#define SS 128
#define QQ 256
#define CC 256
#define HH 8
#define CHD 32
#define MROWS (SS*QQ)

// ---------------------------------------------------------------------------
// Helpers
// ---------------------------------------------------------------------------
__device__ __forceinline__ uint32_t smem_u32(const void* p) {
    uint32_t a;
    asm("{ .reg .u64 t; cvta.to.shared.u64 t, %1; cvt.u32.u64 %0, t; }" : "=r"(a) : "l"(p));
    return a;
}
__device__ __forceinline__ void cp16(uint32_t dst, const void* src) {
    asm volatile("cp.async.cg.shared.global [%0], [%1], 16;" :: "r"(dst), "l"(src));
}
__device__ __forceinline__ void ldmx4(uint32_t* f, uint32_t addr) {
    asm volatile("ldmatrix.sync.aligned.m8n8.x4.shared.b16 {%0,%1,%2,%3}, [%4];"
                 : "=r"(f[0]), "=r"(f[1]), "=r"(f[2]), "=r"(f[3]) : "r"(addr));
}
__device__ __forceinline__ void mma16816(float* c, const uint32_t* a, uint32_t b0, uint32_t b1) {
    asm volatile("mma.sync.aligned.m16n8k16.row.col.f32.bf16.bf16.f32 "
                 "{%0,%1,%2,%3}, {%4,%5,%6,%7}, {%8,%9}, {%0,%1,%2,%3};"
                 : "+f"(c[0]), "+f"(c[1]), "+f"(c[2]), "+f"(c[3])
                 : "r"(a[0]), "r"(a[1]), "r"(a[2]), "r"(a[3]), "r"(b0), "r"(b1));
}
__device__ __forceinline__ uint32_t packbf(float hi, float lo) {
    uint32_t pk;
    asm("cvt.rn.satfinite.bf16x2.f32 %0, %1, %2;" : "=r"(pk) : "f"(hi), "f"(lo));
    return pk;
}

// ---------------------------------------------------------------------------
// Scratch (device globals: allocation-free rule)
// ---------------------------------------------------------------------------
__device__ __nv_bfloat16 g_xb[MROWS * 256];        // input in bf16
__device__ __nv_bfloat16 g_wb[1024 * 256];         // packed wq|wk|wv|wg (wq pre-scaled)
__device__ __nv_bfloat16 g_wob[256 * 256];         // wo in bf16
__device__ __nv_bfloat16 g_qb[SS * HH * QQ * CHD]; // [s,h,q,d] bf16
__device__ __nv_bfloat16 g_kb[SS * HH * QQ * CHD];
__device__ __nv_bfloat16 g_vb[SS * HH * QQ * CHD];
__device__ __nv_bfloat16 g_gateb[MROWS * 256];     // sigmoid gate (bf16), [row, e]
__device__ __nv_bfloat16 g_ob[MROWS * 256];        // gated attention output (bf16)
__device__ __nv_bfloat16 g_biasb[HH * QQ * QQ];    // bias in bf16

// ---------------------------------------------------------------------------
// Prologue conversions
// ---------------------------------------------------------------------------
__global__ void conv_x(const float* __restrict__ x) {
    int i = blockIdx.x * blockDim.x + threadIdx.x;  // per 4 elements
    float4 v = ((const float4*)x)[i];
    __nv_bfloat162* dst = (__nv_bfloat162*)g_xb;
    dst[2 * i]     = __floats2bfloat162_rn(v.x, v.y);
    dst[2 * i + 1] = __floats2bfloat162_rn(v.z, v.w);
}

__global__ void conv_bias(const float* __restrict__ bias) {
    int i = blockIdx.x * blockDim.x + threadIdx.x;  // per 4 elements
    float4 v = ((const float4*)bias)[i];
    __nv_bfloat162* dst = (__nv_bfloat162*)g_biasb;
    dst[2 * i]     = __floats2bfloat162_rn(v.x, v.y);
    dst[2 * i + 1] = __floats2bfloat162_rn(v.z, v.w);
}

__global__ void pack_w(const float* __restrict__ wq, const float* __restrict__ wk,
                       const float* __restrict__ wv, const float* __restrict__ wg,
                       const float* __restrict__ wo) {
    int e = blockIdx.x;
    int c = threadIdx.x;
    if (e < 1024) {
        float val;
        if (e < 256)      val = wq[e * 256 + c] * 0.17677669529663687f;
        else if (e < 512) val = wk[(e - 256) * 256 + c];
        else if (e < 768) val = wv[(e - 512) * 256 + c];
        else              val = wg[(e - 768) * 256 + c];
        g_wb[e * 256 + c] = __float2bfloat16(val);
    } else {
        int r = e - 1024;
        g_wob[r * 256 + c] = __float2bfloat16(wo[r * 256 + c]);
    }
}

// ---------------------------------------------------------------------------
// GEMM core: C[128,64] = A[128,256] x B[64,256]^T (NT, bf16, f32 acc)
// 8 warps as 4(M) x 2(N); per warp 32x32 via 2 x 4 m16n8k16 tiles.
// acc = 32 regs/thread -> 3 CTAs/SM. 3-stage cp.async, 1 barrier/iter.
// ---------------------------------------------------------------------------
#define TILE_A 10240            // 128 rows * 80 bytes
#define TILE_BB 5120            // 64 rows * 80 bytes
#define STAGE_B (TILE_A + TILE_BB)
#define GEMM_SMEM (3 * STAGE_B) // 46080

__device__ __forceinline__ void gemm_core(const __nv_bfloat16* __restrict__ gA,
                                          const __nv_bfloat16* __restrict__ gB,
                                          char* smem,
                                          float acc[2][4][4]) {
    const int tid = threadIdx.x, lane = tid & 31, wid = tid >> 5;
    const int wm0 = (wid >> 1) * 32, wn0 = (wid & 1) * 32;
    const uint32_t sbase = smem_u32(smem);

    #pragma unroll
    for (int mt = 0; mt < 2; mt++)
        #pragma unroll
        for (int nt = 0; nt < 4; nt++)
            #pragma unroll
            for (int i = 0; i < 4; i++) acc[mt][nt][i] = 0.f;

    auto load_tile = [&](int buf, int k0) {
        uint32_t st = sbase + buf * STAGE_B;
        #pragma unroll
        for (int j = 0; j < 2; j++) {           // A: 512 chunks
            int idx = tid + j * 256;
            int r = idx >> 2, ch = idx & 3;
            cp16(st + r * 80 + ch * 16, gA + r * 256 + k0 + ch * 8);
        }
        {                                        // B: 256 chunks
            int r = tid >> 2, ch = tid & 3;
            cp16(st + TILE_A + r * 80 + ch * 16, gB + r * 256 + k0 + ch * 8);
        }
        asm volatile("cp.async.commit_group;" ::: "memory");
    };

    load_tile(0, 0);
    load_tile(1, 32);

    #pragma unroll
    for (int kit = 0; kit < 8; kit++) {
        if (kit < 7) {
            asm volatile("cp.async.wait_group 1;" ::: "memory");
        } else {
            asm volatile("cp.async.wait_group 0;" ::: "memory");
        }
        __syncthreads();   // all threads waited -> tile kit visible; compute kit-1 done
        if (kit < 6) {
            load_tile((kit + 2) % 3, (kit + 2) * 32);
        }
        const uint32_t ab = sbase + (kit % 3) * STAGE_B;
        const uint32_t bb = ab + TILE_A;
        #pragma unroll
        for (int kk = 0; kk < 2; kk++) {
            uint32_t af[2][4];
            #pragma unroll
            for (int mt = 0; mt < 2; mt++) {
                int row = wm0 + mt * 16 + (lane & 15);
                int col = kk * 16 + ((lane >> 4) << 3);
                ldmx4(af[mt], ab + row * 80 + col * 2);
            }
            #pragma unroll
            for (int nt2 = 0; nt2 < 2; nt2++) {
                uint32_t bf[4];
                int nrow = wn0 + nt2 * 16 + (lane & 7) + ((lane >> 4) << 3);
                int ncol = kk * 16 + (((lane >> 3) & 1) << 3);
                ldmx4(bf, bb + nrow * 80 + ncol * 2);
                #pragma unroll
                for (int mt = 0; mt < 2; mt++) {
                    mma16816(acc[mt][2 * nt2],     af[mt], bf[0], bf[1]);
                    mma16816(acc[mt][2 * nt2 + 1], af[mt], bf[2], bf[3]);
                }
            }
        }
    }
}

// ---------------------------------------------------------------------------
// GEMM1: Y[32768,1024] = Xb @ Wb^T. BN=64, grid (16, 256).
// Epilogue: q/k/v in bf16 + sigmoid gate (bf16).
// ---------------------------------------------------------------------------
__global__ __launch_bounds__(256, 3) void gemm1_mma(const float* __restrict__ bg) {
    extern __shared__ char dynsm[];
    const int bn = blockIdx.x, bm = blockIdx.y;
    const int lane = threadIdx.x & 31, wid = threadIdx.x >> 5;
    const int wm0 = (wid >> 1) * 32, wn0 = (wid & 1) * 32;

    float acc[2][4][4];
    gemm_core(g_xb + (size_t)bm * 128 * 256, g_wb + (size_t)bn * 64 * 256, dynsm, acc);

    #pragma unroll
    for (int mt = 0; mt < 2; mt++) {
        #pragma unroll
        for (int nt = 0; nt < 4; nt++) {
            #pragma unroll
            for (int half = 0; half < 2; half++) {
                int m = bm * 128 + wm0 + mt * 16 + (lane >> 2) + half * 8;
                int e = bn * 64 + wn0 + nt * 8 + 2 * (lane & 3);
                float v0 = acc[mt][nt][2 * half];
                float v1 = acc[mt][nt][2 * half + 1];
                int s = m >> 8, q = m & 255;
                if (e < 768) {
                    int which = e >> 8;
                    int h = (e >> 5) & 7;
                    int d = e & 31;
                    __nv_bfloat16* dst = (which == 0 ? g_qb : (which == 1 ? g_kb : g_vb)) +
                                         ((size_t)(s * 8 + h) * 256 + q) * 32 + d;
                    *(uint32_t*)dst = packbf(v1, v0);
                } else {
                    int eg = e - 768;
                    float g0 = 1.0f / (1.0f + __expf(-(v0 + bg[eg])));
                    float g1 = 1.0f / (1.0f + __expf(-(v1 + bg[eg + 1])));
                    *(uint32_t*)(g_gateb + (size_t)m * 256 + eg) = packbf(g1, g0);
                }
            }
        }
    }
}

// ---------------------------------------------------------------------------
// GEMM2: out[q,s,c] = addt + g_ob @ wo^T + bo. BN=64, grid (4, 256).
// ---------------------------------------------------------------------------
__global__ __launch_bounds__(256, 3) void gemm2_mma(const float* __restrict__ bo,
                                                    const float* __restrict__ addt,
                                                    float* __restrict__ out) {
    extern __shared__ char dynsm[];
    const int bn = blockIdx.x, bm = blockIdx.y;
    const int lane = threadIdx.x & 31, wid = threadIdx.x >> 5;
    const int wm0 = (wid >> 1) * 32, wn0 = (wid & 1) * 32;

    float acc[2][4][4];
    gemm_core(g_ob + (size_t)bm * 128 * 256, g_wob + (size_t)bn * 64 * 256, dynsm, acc);

    #pragma unroll
    for (int mt = 0; mt < 2; mt++) {
        #pragma unroll
        for (int nt = 0; nt < 4; nt++) {
            #pragma unroll
            for (int half = 0; half < 2; half++) {
                int m = bm * 128 + wm0 + mt * 16 + (lane >> 2) + half * 8;
                int c = bn * 64 + wn0 + nt * 8 + 2 * (lane & 3);
                int s = m >> 8, q = m & 255;
                size_t oi = ((size_t)q * 128 + s) * 256 + c;
                float2 a2 = *(const float2*)(addt + oi);
                float2 b2 = *(const float2*)(bo + c);
                float2 r2;
                r2.x = a2.x + b2.x + acc[mt][nt][2 * half];
                r2.y = a2.y + b2.y + acc[mt][nt][2 * half + 1];
                *(float2*)(out + oi) = r2;
            }
        }
    }
}

// ---------------------------------------------------------------------------
// Tensor-core flash attention. One CTA per (s,h), 8 warps x 32 q-rows.
// ---------------------------------------------------------------------------
#define QS_OFF   0         // 256 rows x 80B
#define KS_OFF   20480     // 256 rows x 80B
#define VT_OFF   40960     // Vt: 32 rows x 528B
#define MADD_OFF 57856     // 256 floats
#define ATTN_SMEM 58880

__global__ __launch_bounds__(256) void attn_tc(const float* __restrict__ mask) {
    extern __shared__ char smp[];
    const uint32_t sb = smem_u32(smp);
    const int s = blockIdx.x >> 3;
    const int h = blockIdx.x & 7;
    const int t = threadIdx.x;
    const int lane = t & 31, w = t >> 5;

    const size_t hb = (size_t)(s * 8 + h) * 16384;   // byte offset of this (s,h) tile

    // cp.async Q, K tiles into 80B-pitch smem
    #pragma unroll
    for (int j = 0; j < 4; j++) {
        int idx = t + j * 256;
        int r = idx >> 2, ch = idx & 3;
        cp16(sb + QS_OFF + r * 80 + ch * 16, (const char*)g_qb + hb + r * 64 + ch * 16);
        cp16(sb + KS_OFF + r * 80 + ch * 16, (const char*)g_kb + hb + r * 64 + ch * 16);
    }
    asm volatile("cp.async.commit_group;" ::: "memory");

    // V transpose: thread t reads V row k=t (32 bf16), scatters to Vt[d][k=t]
    {
        union { uint4 v4[4]; uint16_t u16[32]; } tv;
        const uint4* vr = (const uint4*)((const char*)g_vb + hb + t * 64);
        tv.v4[0] = vr[0]; tv.v4[1] = vr[1]; tv.v4[2] = vr[2]; tv.v4[3] = vr[3];
        #pragma unroll
        for (int d = 0; d < 32; d++)
            *(uint16_t*)(smp + VT_OFF + d * 528 + 2 * t) = tv.u16[d];
    }
    // mask additive term
    *(float*)(smp + MADD_OFF + 4 * t) = (mask[s * 256 + t] - 1.0f) * 1e9f;

    asm volatile("cp.async.wait_group 0;" ::: "memory");
    __syncthreads();

    // Q fragments for this warp's 32 rows
    uint32_t af[2][2][4];   // [mt][kstep]
    #pragma unroll
    for (int mt = 0; mt < 2; mt++)
        #pragma unroll
        for (int ks = 0; ks < 2; ks++) {
            int row = 32 * w + mt * 16 + (lane & 15);
            int col = ks * 16 + ((lane >> 4) << 3);
            ldmx4(af[mt][ks], sb + QS_OFF + row * 80 + col * 2);
        }

    float o_acc[2][4][4];
    #pragma unroll
    for (int mt = 0; mt < 2; mt++)
        #pragma unroll
        for (int nt = 0; nt < 4; nt++)
            #pragma unroll
            for (int i = 0; i < 4; i++) o_acc[mt][nt][i] = 0.f;
    float lsum[2][2] = {};

    const int r_lo = (lane >> 2);         // row-in-tile for c0,c1
    const int jo   = 2 * (lane & 3);      // col pair offset

    for (int c = 0; c < 8; c++) {
        // ---- S = Q K^T for this 32-key chunk ----
        float s_acc[2][4][4];
        #pragma unroll
        for (int mt = 0; mt < 2; mt++)
            #pragma unroll
            for (int nt = 0; nt < 4; nt++)
                #pragma unroll
                for (int i = 0; i < 4; i++) s_acc[mt][nt][i] = 0.f;

        #pragma unroll
        for (int ks = 0; ks < 2; ks++) {
            #pragma unroll
            for (int nt2 = 0; nt2 < 2; nt2++) {
                uint32_t bf[4];
                int nrow = c * 32 + nt2 * 16 + (lane & 7) + ((lane >> 4) << 3);
                int ncol = ks * 16 + (((lane >> 3) & 1) << 3);
                ldmx4(bf, sb + KS_OFF + nrow * 80 + ncol * 2);
                #pragma unroll
                for (int mt = 0; mt < 2; mt++) {
                    mma16816(s_acc[mt][2 * nt2],     af[mt][ks], bf[0], bf[1]);
                    mma16816(s_acc[mt][2 * nt2 + 1], af[mt][ks], bf[2], bf[3]);
                }
            }
        }

        // ---- bias(bf16) + mask, exp, pack P fragments ----
        uint32_t pfrag[2][4][2];
        #pragma unroll
        for (int mt = 0; mt < 2; mt++) {
            int r0 = 32 * w + mt * 16 + r_lo;
            #pragma unroll
            for (int nt = 0; nt < 4; nt++) {
                int j = c * 32 + nt * 8 + jo;
                float2 mj = *(const float2*)(smp + MADD_OFF + 4 * j);
                __nv_bfloat162 bb0 = *(const __nv_bfloat162*)(g_biasb + ((size_t)(h * 256 + r0) * 256 + j));
                __nv_bfloat162 bb1 = *(const __nv_bfloat162*)(g_biasb + ((size_t)(h * 256 + r0 + 8) * 256 + j));
                float2 b0 = __bfloat1622float2(bb0);
                float2 b1 = __bfloat1622float2(bb1);
                float w00 = __expf(fminf(s_acc[mt][nt][0] + b0.x + mj.x, 80.f));
                float w01 = __expf(fminf(s_acc[mt][nt][1] + b0.y + mj.y, 80.f));
                float w10 = __expf(fminf(s_acc[mt][nt][2] + b1.x + mj.x, 80.f));
                float w11 = __expf(fminf(s_acc[mt][nt][3] + b1.y + mj.y, 80.f));
                lsum[mt][0] += w00 + w01;
                lsum[mt][1] += w10 + w11;
                pfrag[mt][nt][0] = packbf(w01, w00);
                pfrag[mt][nt][1] = packbf(w11, w10);
            }
        }

        // ---- O += P V ----
        #pragma unroll
        for (int ks2 = 0; ks2 < 2; ks2++) {
            uint32_t bv[2][4];
            #pragma unroll
            for (int nv = 0; nv < 2; nv++) {
                int nrow = nv * 16 + (lane & 7) + ((lane >> 4) << 3);
                int ncol = c * 32 + ks2 * 16 + (((lane >> 3) & 1) << 3);
                ldmx4(bv[nv], sb + VT_OFF + nrow * 528 + ncol * 2);
            }
            #pragma unroll
            for (int mt = 0; mt < 2; mt++) {
                uint32_t aP[4] = { pfrag[mt][2 * ks2][0], pfrag[mt][2 * ks2][1],
                                   pfrag[mt][2 * ks2 + 1][0], pfrag[mt][2 * ks2 + 1][1] };
                #pragma unroll
                for (int nv = 0; nv < 2; nv++) {
                    mma16816(o_acc[mt][2 * nv],     aP, bv[nv][0], bv[nv][1]);
                    mma16816(o_acc[mt][2 * nv + 1], aP, bv[nv][2], bv[nv][3]);
                }
            }
        }
    }

    // ---- row-sum reduce + normalize + gate + store ----
    float inv[2][2];
    #pragma unroll
    for (int mt = 0; mt < 2; mt++)
        #pragma unroll
        for (int half = 0; half < 2; half++) {
            float lv = lsum[mt][half];
            lv += __shfl_xor_sync(0xffffffffu, lv, 1);
            lv += __shfl_xor_sync(0xffffffffu, lv, 2);
            inv[mt][half] = 1.0f / lv;
        }

    #pragma unroll
    for (int mt = 0; mt < 2; mt++) {
        int q0 = 32 * w + mt * 16 + r_lo;
        int row0 = s * 256 + q0;
        #pragma unroll
        for (int nv = 0; nv < 4; nv++) {
            int d = nv * 8 + jo;
            __nv_bfloat162 gav = *(const __nv_bfloat162*)(g_gateb + (size_t)row0 * 256 + h * 32 + d);
            __nv_bfloat162 gbv = *(const __nv_bfloat162*)(g_gateb + (size_t)(row0 + 8) * 256 + h * 32 + d);
            float2 ga = __bfloat1622float2(gav);
            float2 gb = __bfloat1622float2(gbv);
            float v00 = o_acc[mt][nv][0] * inv[mt][0] * ga.x;
            float v01 = o_acc[mt][nv][1] * inv[mt][0] * ga.y;
            float v10 = o_acc[mt][nv][2] * inv[mt][1] * gb.x;
            float v11 = o_acc[mt][nv][3] * inv[mt][1] * gb.y;
            *(uint32_t*)(g_ob + (size_t)row0 * 256 + h * 32 + d) = packbf(v01, v00);
            *(uint32_t*)(g_ob + (size_t)(row0 + 8) * 256 + h * 32 + d) = packbf(v11, v10);
        }
    }
}

// ---------------------------------------------------------------------------
extern "C" void kernel_launch(void* const* d_in, const int* in_sizes, int n_in,
                              void* d_out, int out_size) {
    const float* x    = (const float*)d_in[0];
    const float* mask = (const float*)d_in[1];
    const float* bias = (const float*)d_in[2];
    const float* addt = (const float*)d_in[3];
    const float* wq   = (const float*)d_in[4];
    const float* wk   = (const float*)d_in[5];
    const float* wv   = (const float*)d_in[6];
    const float* wg   = (const float*)d_in[7];
    const float* bg   = (const float*)d_in[8];
    const float* wo   = (const float*)d_in[9];
    const float* bo   = (const float*)d_in[10];
    float* out = (float*)d_out;

    cudaFuncSetAttribute(attn_tc, cudaFuncAttributeMaxDynamicSharedMemorySize, ATTN_SMEM);
    cudaFuncSetAttribute(gemm1_mma, cudaFuncAttributeMaxDynamicSharedMemorySize, GEMM_SMEM);
    cudaFuncSetAttribute(gemm2_mma, cudaFuncAttributeMaxDynamicSharedMemorySize, GEMM_SMEM);

    conv_x<<<(MROWS * 256 / 4 + 255) / 256, 256>>>(x);
    conv_bias<<<(HH * QQ * QQ / 4 + 255) / 256, 256>>>(bias);
    pack_w<<<1280, 256>>>(wq, wk, wv, wg, wo);

    gemm1_mma<<<dim3(16, 256), 256, GEMM_SMEM>>>(bg);
    attn_tc<<<1024, 256, ATTN_SMEM>>>(mask);
    gemm2_mma<<<dim3(4, 256), 256, GEMM_SMEM>>>(bo, addt, out);
}